// round 16
// baseline (speedup 1.0000x reference)
#include <cuda_runtime.h>
#include <cuda_fp16.h>
#include <math.h>
#include <stdint.h>

#define B_   8
#define N_   2048
#define M_   512
#define C_   256
#define NR_  4
#define CNT_ (B_*NR_*N_)

// ---------------- scratch ----------------
__device__ float g_G [B_*NR_*M_*C_];   // [z][m][o] o-contiguous
__device__ float g_y1[B_*NR_*C_*N_];   // [z][c][n] n-contiguous
__device__ int   g_idx[B_*N_*3];
__device__ float g_w  [B_*N_*3];
__device__ float g_s1[C_], g_q1[C_], g_s2[C_], g_q2[C_];
__device__ float g_scale1[C_], g_bias1[C_], g_scale2[C_], g_bias2[C_];
__device__ int   g_tk[4];              // work-stealing tickets (G, Y1, Z)

// ---------------- helpers ----------------
__device__ __forceinline__ unsigned pack2(float lo, float hi) {
    __half2 h = __floats2half2_rn(lo, hi);
    return *reinterpret_cast<unsigned*>(&h);
}
__device__ __forceinline__ void hmma16(float* c, const unsigned* a, const unsigned* b) {
    asm volatile("mma.sync.aligned.m16n8k16.row.col.f32.f16.f16.f32 "
        "{%0,%1,%2,%3}, {%4,%5,%6,%7}, {%8,%9}, {%0,%1,%2,%3};"
        : "+f"(c[0]), "+f"(c[1]), "+f"(c[2]), "+f"(c[3])
        : "r"(a[0]), "r"(a[1]), "r"(a[2]), "r"(a[3]), "r"(b[0]), "r"(b[1]));
}

// ---------------- smem layout (32-bit words), per CTA ----------------
// Block tile 128(o) x 64(n). Stage aliases the Ys epilogue buffer.
#define APW 12                 // A row pitch: 8 f16x2 words + 4 pad
#define BPW 72                 // B row pitch: 32 f16x2... (64 words) + 8 pad
#define OFF_BW (128*APW)       // 1536 : B stage after A stage (stage = 2112 w)
#define YP  129                // Ys pitch (odd)
#define OFF_S (64*YP)          // 8256 : stats sum (128)
#define OFF_Q (OFF_S + 128)    // 8384
#define OFF_W (OFF_Q + 128)    // 8512 : interp weights (192)
#define OFF_I (OFF_W + 192)    // 8704 : interp indices (192)
#define OFF_T (OFF_I + 192)    // 8896 : s_tile
#define SMEMF (OFF_T + 8)
#define SMEM_BYTES (SMEMF * 4) // ~35.6 KB

#define NT_Y (32*2*32)         // 2048 tiles (z32 x o2 x n32)
#define NT_G (32*2*8)          // 512 tiles  (z32 x o2 x m8)
#define GRID_P 444

// ---------------- small kernels ----------------
__global__ void zero_stats_kernel() {
    int t = threadIdx.x;
    g_s1[t] = 0.f; g_q1[t] = 0.f; g_s2[t] = 0.f; g_q2[t] = 0.f;
    if (t < 4) g_tk[t] = 0;
}

__global__ void knn_kernel(const float* __restrict__ unknown,
                           const float* __restrict__ known) {
    __shared__ float ks[M_*3];
    int b = blockIdx.y;
    const float* kb = known + (size_t)b * M_ * 3;
    for (int i = threadIdx.x; i < M_*3; i += blockDim.x) ks[i] = kb[i];
    __syncthreads();
    int n = blockIdx.x * blockDim.x + threadIdx.x;
    const float* u = unknown + ((size_t)b * N_ + n) * 3;
    float ux = u[0], uy = u[1], uz = u[2];
    float d0 = 3.4e38f, d1 = 3.4e38f, d2 = 3.4e38f;
    int   i0 = 0, i1 = 0, i2 = 0;
    for (int m = 0; m < M_; m++) {
        float dx = ux - ks[m*3], dy = uy - ks[m*3+1], dz = uz - ks[m*3+2];
        float d  = dx*dx + dy*dy + dz*dz;
        if (d < d2) {
            if (d < d0)      { d2=d1; i2=i1; d1=d0; i1=i0; d0=d; i0=m; }
            else if (d < d1) { d2=d1; i2=i1; d1=d;  i1=m; }
            else             { d2=d;  i2=m; }
        }
    }
    float r0 = 1.f / (sqrtf(fmaxf(d0, 0.f)) + 1e-8f);
    float r1 = 1.f / (sqrtf(fmaxf(d1, 0.f)) + 1e-8f);
    float r2 = 1.f / (sqrtf(fmaxf(d2, 0.f)) + 1e-8f);
    float inv = 1.f / (r0 + r1 + r2);
    int base = (b * N_ + n) * 3;
    g_idx[base] = i0; g_idx[base+1] = i1; g_idx[base+2] = i2;
    g_w[base] = r0*inv; g_w[base+1] = r1*inv; g_w[base+2] = r2*inv;
}

__global__ void bnfin_kernel(const float* __restrict__ gamma,
                             const float* __restrict__ beta, int which) {
    int t = threadIdx.x;
    float s = which ? g_s2[t] : g_s1[t];
    float q = which ? g_q2[t] : g_q1[t];
    float mean = s * (1.f / CNT_);
    float var  = q * (1.f / CNT_) - mean * mean;
    float sc = gamma[t] * rsqrtf(var + 1e-5f);
    float bi = beta[t] - mean * sc;
    if (which) { g_scale2[t] = sc; g_bias2[t] = bi; }
    else       { g_scale1[t] = sc; g_bias1[t] = bi; }
}

__global__ void out_kernel(float* __restrict__ out) {
    int i = blockIdx.x * blockDim.x + threadIdx.x;
    int o = (i >> 11) & 255;
    float sc = g_scale2[o], bi = g_bias2[o];
    float4 v = ((float4*)out)[i];
    v.x = fmaxf(fmaf(v.x, sc, bi), 0.f);
    v.y = fmaxf(fmaf(v.y, sc, bi), 0.f);
    v.z = fmaxf(fmaf(v.z, sc, bi), 0.f);
    v.w = fmaxf(fmaf(v.w, sc, bi), 0.f);
    ((float4*)out)[i] = v;
}

// ---------------- GEMM core (fp16 m16n8k16, tile 128o x 64n) ----------------
// 8 warps as (wo 0..3)x(wn 0..1); warp tile 32o x 32n = 2 mtiles x 4 ntiles.
// A: As[o(128)][APW] f16x2. B: Bs[k2(8)][BPW] f16x2 (k-pair packed).

__device__ __forceinline__ void ldgA(const float* W, int ws, int o0, int c, int tid,
                                     float4* ra) {
    const float* s = W + (size_t)(o0 + (tid & 127)) * ws + c*16 + (tid >> 7) * 8;
    ra[0] = *(const float4*)s; ra[1] = *(const float4*)(s + 4);
}
__device__ __forceinline__ void stsA(unsigned* As, const float4* ra, int tid) {
    unsigned w0[4];
    w0[0] = pack2(ra[0].x, ra[0].y); w0[1] = pack2(ra[0].z, ra[0].w);
    w0[2] = pack2(ra[1].x, ra[1].y); w0[3] = pack2(ra[1].z, ra[1].w);
    *(uint4*)(As + (tid & 127)*APW + (tid >> 7) * 4) = *(uint4*)w0;
}
__device__ __forceinline__ void ldgB(const float* X, int cs, int c, int tid,
                                     float2& r0, float2& r1) {
    int k2 = tid >> 5, ng = (tid & 31) * 2;
    const float* s = X + (size_t)(c*16 + 2*k2) * cs + ng;
    r0 = *(const float2*)s;
    r1 = *(const float2*)(s + cs);
}
__device__ __forceinline__ void stsB(unsigned* Bs, float2 r0, float2 r1, int tid) {
    int k2 = tid >> 5, ng = (tid & 31) * 2;
    unsigned w[2];
    w[0] = pack2(r0.x, r1.x); w[1] = pack2(r0.y, r1.y);
    *(uint2*)(Bs + k2*BPW + ng) = *(uint2*)w;
}

__device__ __forceinline__ void frag_mma16(const unsigned* As, const unsigned* Bs,
                                           int wo, int wn, int g, int t,
                                           float acc[2][4][4]) {
    unsigned af[2][4], bf[4][2];
    #pragma unroll
    for (int mi = 0; mi < 2; mi++) {
        int row = wo*32 + mi*16 + g;
        af[mi][0] = As[row*APW + t];
        af[mi][1] = As[(row+8)*APW + t];
        af[mi][2] = As[row*APW + t + 4];
        af[mi][3] = As[(row+8)*APW + t + 4];
    }
    #pragma unroll
    for (int ni = 0; ni < 4; ni++) {
        int nb = wn*32 + ni*8 + g;
        bf[ni][0] = Bs[t*BPW + nb];
        bf[ni][1] = Bs[(t+4)*BPW + nb];
    }
    #pragma unroll
    for (int mi = 0; mi < 2; mi++)
        #pragma unroll
        for (int ni = 0; ni < 4; ni++)
            hmma16(acc[mi][ni], af[mi], bf[ni]);
}

__device__ __forceinline__ void mainloop16(float* sm, const float* W, int ws, int o0,
                                           const float* X, int cs,
                                           float acc[2][4][4]) {
    int tid = threadIdx.x, lane = tid & 31, w = tid >> 5;
    int wo = w >> 1, wn = w & 1, g = lane >> 2, t = lane & 3;
    unsigned* As = (unsigned*)sm;
    unsigned* Bs = As + OFF_BW;
    float4 ra[2]; float2 rb0, rb1;
    ldgA(W, ws, o0, 0, tid, ra);
    ldgB(X, cs, 0, tid, rb0, rb1);
    for (int c = 0; c < 16; c++) {
        stsA(As, ra, tid);
        stsB(Bs, rb0, rb1, tid);
        __syncthreads();
        if (c < 15) {
            ldgA(W, ws, o0, c+1, tid, ra);
            ldgB(X, cs, c+1, tid, rb0, rb1);
        }
        frag_mma16(As, Bs, wo, wn, g, t, acc);
        __syncthreads();
    }
}

__device__ __forceinline__ void acc_to_ys(float* sm, float acc[2][4][4],
                                          int wo, int wn, int g, int t) {
    #pragma unroll
    for (int mi = 0; mi < 2; mi++)
        #pragma unroll
        for (int ni = 0; ni < 4; ni++) {
            int orow = wo*32 + mi*16 + g;
            int ncol = wn*32 + ni*8 + 2*t;
            sm[ncol*YP + orow]       = acc[mi][ni][0];
            sm[(ncol+1)*YP + orow]   = acc[mi][ni][1];
            sm[ncol*YP + orow+8]     = acc[mi][ni][2];
            sm[(ncol+1)*YP + orow+8] = acc[mi][ni][3];
        }
}

// ---------------- gemmG: G[z][m][o] = W1a @ kf (persistent tiles) ----------------
__global__ __launch_bounds__(256, 3) void gemmG(const float* __restrict__ kf,
                                                const float* __restrict__ W1) {
    extern __shared__ float sm[];
    int tid = threadIdx.x, lane = tid & 31, w = tid >> 5;
    int wo = w >> 1, wn = w & 1, g = lane >> 2, t = lane & 3;
    volatile int* s_tile = (volatile int*)(sm + OFF_T);
    for (;;) {
        if (tid == 0) *s_tile = atomicAdd(&g_tk[0], 1);
        __syncthreads();
        int tile = *s_tile;
        if (tile >= NT_G) break;
        int z = tile >> 4, o0 = ((tile >> 3) & 1) * 128, m0 = (tile & 7) * 64;
        int b = z >> 2, r = z & 3;
        float acc[2][4][4] = {};
        const float* X = kf + (size_t)b * (C_*NR_*M_) + (size_t)r * M_ + m0;
        mainloop16(sm, W1, 512, o0, X, NR_*M_, acc);
        acc_to_ys(sm, acc, wo, wn, g, t);
        __syncthreads();
        float* Gz = g_G + ((size_t)z * M_ + m0) * C_ + o0;
        for (int it = 0; it < 8; it++) {
            int m = it*8 + w;
            #pragma unroll
            for (int j = 0; j < 4; j++) {
                int o = lane + 32*j;
                Gz[(size_t)m * C_ + o] = sm[m*YP + o];
            }
        }
        __syncthreads();
    }
}

// ---------------- gemmY1: y1 = W1b@uf + gather(G); BN1 stats ----------------
__global__ __launch_bounds__(256, 3) void gemmY1(const float* __restrict__ uf,
                                                 const float* __restrict__ W1) {
    extern __shared__ float sm[];
    int tid = threadIdx.x, lane = tid & 31, w = tid >> 5;
    int wo = w >> 1, wn = w & 1, g = lane >> 2, t = lane & 3;
    volatile int* s_tile = (volatile int*)(sm + OFF_T);
    for (;;) {
        if (tid == 0) *s_tile = atomicAdd(&g_tk[1], 1);
        __syncthreads();
        int tile = *s_tile;
        if (tile >= NT_Y) break;
        int z = tile >> 6, o0 = ((tile >> 5) & 1) * 128, n0 = (tile & 31) * 64;
        int b = z >> 2, r = z & 3;
        float acc[2][4][4] = {};
        const float* X = uf + (size_t)b * (C_*NR_*N_) + (size_t)r * N_ + n0;
        mainloop16(sm, W1 + 256, 512, o0, X, NR_*N_, acc);
        acc_to_ys(sm, acc, wo, wn, g, t);
        // load interp data + zero local stats
        if (tid < 192) {
            sm[OFF_W + tid]         = g_w  [(b * N_ + n0) * 3 + tid];
            ((int*)sm)[OFF_I + tid] = g_idx[(b * N_ + n0) * 3 + tid];
        }
        if (tid < 128) { sm[OFF_S + tid] = 0.f; sm[OFF_Q + tid] = 0.f; }
        __syncthreads();
        // gather + BN1 stats (warp-per-n, lane-per-o)
        const float* Gz = g_G + (size_t)z * M_ * C_ + o0;
        float s4[4] = {}, q4[4] = {};
        for (int it = 0; it < 8; it++) {
            int n = it*8 + w;
            float w0 = sm[OFF_W + n*3], w1 = sm[OFF_W + n*3+1], w2 = sm[OFF_W + n*3+2];
            const float* G0 = Gz + (size_t)((int*)sm)[OFF_I + n*3]     * C_;
            const float* G1 = Gz + (size_t)((int*)sm)[OFF_I + n*3 + 1] * C_;
            const float* G2 = Gz + (size_t)((int*)sm)[OFF_I + n*3 + 2] * C_;
            #pragma unroll
            for (int j = 0; j < 4; j++) {
                int o = lane + 32*j;
                float v = sm[n*YP + o] + w0*G0[o] + w1*G1[o] + w2*G2[o];
                sm[n*YP + o] = v;
                s4[j] += v; q4[j] += v*v;
            }
        }
        #pragma unroll
        for (int j = 0; j < 4; j++) {
            atomicAdd(&sm[OFF_S + lane + 32*j], s4[j]);
            atomicAdd(&sm[OFF_Q + lane + 32*j], q4[j]);
        }
        __syncthreads();
        if (tid < 128) {
            atomicAdd(&g_s1[o0 + tid], sm[OFF_S + tid]);
            atomicAdd(&g_q1[o0 + tid], sm[OFF_Q + tid]);
        }
        float* y1z = g_y1 + (size_t)z * C_ * N_ + (size_t)o0 * N_ + n0;
        for (int it = 0; it < 16; it++) {
            int o = it*8 + w;
            #pragma unroll
            for (int j = 0; j < 2; j++) {
                int n = lane + 32*j;
                y1z[(size_t)o * N_ + n] = sm[n*YP + o];
            }
        }
        __syncthreads();
    }
}

// ---------------- gemmZ: out = W2 @ relu(bn1(y1)); BN2 stats ----------------
__global__ __launch_bounds__(256, 3) void gemmZ(const float* __restrict__ W2,
                                                float* __restrict__ out) {
    extern __shared__ float sm[];
    int tid = threadIdx.x, lane = tid & 31, w = tid >> 5;
    int wo = w >> 1, wn = w & 1, g = lane >> 2, t = lane & 3;
    int k2 = tid >> 5;
    unsigned* As = (unsigned*)sm;
    unsigned* Bs = As + OFF_BW;
    volatile int* s_tile = (volatile int*)(sm + OFF_T);
    for (;;) {
        if (tid == 0) *s_tile = atomicAdd(&g_tk[2], 1);
        __syncthreads();
        int tile = *s_tile;
        if (tile >= NT_Y) break;
        int z = tile >> 6, o0 = ((tile >> 5) & 1) * 128, n0 = (tile & 31) * 64;
        int b = z >> 2, r = z & 3;
        float acc[2][4][4] = {};
        const float* y1z = g_y1 + (size_t)z * C_ * N_ + n0;
        float4 ra[2]; float2 rb0, rb1;
        ldgA(W2, 256, o0, 0, tid, ra);
        ldgB(y1z, N_, 0, tid, rb0, rb1);
        for (int c = 0; c < 16; c++) {
            {   // BN1 + ReLU fused into f16 pack
                float sc0 = g_scale1[c*16 + 2*k2],     bi0 = g_bias1[c*16 + 2*k2];
                float sc1 = g_scale1[c*16 + 2*k2 + 1], bi1 = g_bias1[c*16 + 2*k2 + 1];
                float2 v0 = rb0, v1 = rb1;
                v0.x = fmaxf(fmaf(v0.x, sc0, bi0), 0.f); v0.y = fmaxf(fmaf(v0.y, sc0, bi0), 0.f);
                v1.x = fmaxf(fmaf(v1.x, sc1, bi1), 0.f); v1.y = fmaxf(fmaf(v1.y, sc1, bi1), 0.f);
                stsB(Bs, v0, v1, tid);
            }
            stsA(As, ra, tid);
            __syncthreads();
            if (c < 15) {
                ldgA(W2, 256, o0, c+1, tid, ra);
                ldgB(y1z, N_, c+1, tid, rb0, rb1);
            }
            frag_mma16(As, Bs, wo, wn, g, t, acc);
            __syncthreads();
        }
        // BN2 stats from pre-BN accumulators
        if (tid < 128) { sm[OFF_S + tid] = 0.f; sm[OFF_Q + tid] = 0.f; }
        __syncthreads();
        #pragma unroll
        for (int mi = 0; mi < 2; mi++) {
            float sa = 0.f, qa = 0.f, sb = 0.f, qb = 0.f;
            #pragma unroll
            for (int ni = 0; ni < 4; ni++) {
                float a0 = acc[mi][ni][0], a1 = acc[mi][ni][1];
                float a2 = acc[mi][ni][2], a3 = acc[mi][ni][3];
                sa += a0 + a1;  qa += a0*a0 + a1*a1;
                sb += a2 + a3;  qb += a2*a2 + a3*a3;
            }
            int orow = wo*32 + mi*16 + g;
            atomicAdd(&sm[OFF_S + orow],     sa);
            atomicAdd(&sm[OFF_Q + orow],     qa);
            atomicAdd(&sm[OFF_S + orow + 8], sb);
            atomicAdd(&sm[OFF_Q + orow + 8], qb);
        }
        __syncthreads();
        if (tid < 128) {
            atomicAdd(&g_s2[o0 + tid], sm[OFF_S + tid]);
            atomicAdd(&g_q2[o0 + tid], sm[OFF_Q + tid]);
        }
        __syncthreads();
        acc_to_ys(sm, acc, wo, wn, g, t);
        __syncthreads();
        float* ob = out + ((size_t)(b*256 + o0) * 4 + r) * 2048 + n0;
        for (int it = 0; it < 16; it++) {
            int o = it*8 + w;
            #pragma unroll
            for (int j = 0; j < 2; j++) {
                int n = lane + 32*j;
                ob[(size_t)o * (4*2048) + n] = sm[n*YP + o];
            }
        }
        __syncthreads();
    }
}

// ---------------- launch ----------------
extern "C" void kernel_launch(void* const* d_in, const int* in_sizes, int n_in,
                              void* d_out, int out_size) {
    const float* unknown = (const float*)d_in[0];
    const float* known   = (const float*)d_in[1];
    const float* uf      = (const float*)d_in[2];
    const float* kf      = (const float*)d_in[3];
    const float* W1      = (const float*)d_in[4];
    const float* g1      = (const float*)d_in[5];
    const float* b1      = (const float*)d_in[6];
    const float* W2      = (const float*)d_in[7];
    const float* g2      = (const float*)d_in[8];
    const float* b2      = (const float*)d_in[9];
    float* out = (float*)d_out;

    static int inited = 0;
    if (!inited) {
        cudaFuncSetAttribute(gemmG,  cudaFuncAttributeMaxDynamicSharedMemorySize, SMEM_BYTES);
        cudaFuncSetAttribute(gemmY1, cudaFuncAttributeMaxDynamicSharedMemorySize, SMEM_BYTES);
        cudaFuncSetAttribute(gemmZ,  cudaFuncAttributeMaxDynamicSharedMemorySize, SMEM_BYTES);
        inited = 1;
    }

    zero_stats_kernel<<<1, 256>>>();
    knn_kernel<<<dim3(N_/256, B_), 256>>>(unknown, known);
    gemmG<<<GRID_P, 256, SMEM_BYTES>>>(kf, W1);
    gemmY1<<<GRID_P, 256, SMEM_BYTES>>>(uf, W1);
    bnfin_kernel<<<1, 256>>>(g1, b1, 0);
    gemmZ<<<GRID_P, 256, SMEM_BYTES>>>(W2, out);
    bnfin_kernel<<<1, 256>>>(g2, b2, 1);
    out_kernel<<<(B_*256*NR_*N_/4) / 256, 256>>>(out);
}

// round 17
// speedup vs baseline: 1.2954x; 1.2954x over previous
#include <cuda_runtime.h>
#include <cuda_fp16.h>
#include <math.h>
#include <stdint.h>

#define B_   8
#define N_   2048
#define M_   512
#define C_   256
#define NR_  4
#define CNT_ (B_*NR_*N_)

// ---------------- scratch ----------------
__device__ float g_G [B_*NR_*M_*C_];   // [z][m][o] o-contiguous
__device__ float g_y1[B_*NR_*C_*N_];   // [z][c][n] n-contiguous
__device__ int   g_idx[B_*N_*3];
__device__ float g_w  [B_*N_*3];
__device__ float g_s1[C_], g_q1[C_], g_s2[C_], g_q2[C_];
__device__ float g_scale1[C_], g_bias1[C_], g_scale2[C_], g_bias2[C_];
__device__ int   g_tk[4];              // work-stealing tickets (G, Y1, Z)

// ---------------- helpers ----------------
__device__ __forceinline__ unsigned pack2(float lo, float hi) {
    __half2 h = __floats2half2_rn(lo, hi);
    return *reinterpret_cast<unsigned*>(&h);
}
__device__ __forceinline__ void hmma16(float* c, const unsigned* a, const unsigned* b) {
    asm volatile("mma.sync.aligned.m16n8k16.row.col.f32.f16.f16.f32 "
        "{%0,%1,%2,%3}, {%4,%5,%6,%7}, {%8,%9}, {%0,%1,%2,%3};"
        : "+f"(c[0]), "+f"(c[1]), "+f"(c[2]), "+f"(c[3])
        : "r"(a[0]), "r"(a[1]), "r"(a[2]), "r"(a[3]), "r"(b[0]), "r"(b[1]));
}

// ---------------- smem layout (32-bit words), per CTA ----------------
// Block tile 128(o) x 128(n), K chunk 16. TWO stage buffers (double-buffered),
// both aliased by the Ys epilogue region.
#define APW 12                 // A row pitch: 8 f16x2 words + 4 pad
#define BPW 136                // B row pitch: 128 words + 8 pad
#define OFF_BW (128*APW)       // 1536 : B after A within a stage
#define STG 2624               // stage stride in words (A 1536 + B 1088)
#define YP  129                // Ys pitch (odd)
#define OFF_S (128*YP)         // 16512
#define OFF_Q (OFF_S + 128)
#define OFF_W (OFF_Q + 128)
#define OFF_I (OFF_W + 384)
#define OFF_T (OFF_I + 384)    // s_tile
#define SMEMF (OFF_T + 8)
#define SMEM_BYTES (SMEMF * 4) // ~70.2 KB

#define NT_Y (2*16*32)         // 1024 tiles (o2 x n16 x z32)
#define NT_G (2*4*32)          // 256 tiles
#define GRID_P 296

// ---------------- small kernels ----------------
__global__ void zero_stats_kernel() {
    int t = threadIdx.x;
    g_s1[t] = 0.f; g_q1[t] = 0.f; g_s2[t] = 0.f; g_q2[t] = 0.f;
    if (t < 4) g_tk[t] = 0;
}

__global__ void knn_kernel(const float* __restrict__ unknown,
                           const float* __restrict__ known) {
    __shared__ float ks[M_*3];
    int b = blockIdx.y;
    const float* kb = known + (size_t)b * M_ * 3;
    for (int i = threadIdx.x; i < M_*3; i += blockDim.x) ks[i] = kb[i];
    __syncthreads();
    int n = blockIdx.x * blockDim.x + threadIdx.x;
    const float* u = unknown + ((size_t)b * N_ + n) * 3;
    float ux = u[0], uy = u[1], uz = u[2];
    float d0 = 3.4e38f, d1 = 3.4e38f, d2 = 3.4e38f;
    int   i0 = 0, i1 = 0, i2 = 0;
    for (int m = 0; m < M_; m++) {
        float dx = ux - ks[m*3], dy = uy - ks[m*3+1], dz = uz - ks[m*3+2];
        float d  = dx*dx + dy*dy + dz*dz;
        if (d < d2) {
            if (d < d0)      { d2=d1; i2=i1; d1=d0; i1=i0; d0=d; i0=m; }
            else if (d < d1) { d2=d1; i2=i1; d1=d;  i1=m; }
            else             { d2=d;  i2=m; }
        }
    }
    float r0 = 1.f / (sqrtf(fmaxf(d0, 0.f)) + 1e-8f);
    float r1 = 1.f / (sqrtf(fmaxf(d1, 0.f)) + 1e-8f);
    float r2 = 1.f / (sqrtf(fmaxf(d2, 0.f)) + 1e-8f);
    float inv = 1.f / (r0 + r1 + r2);
    int base = (b * N_ + n) * 3;
    g_idx[base] = i0; g_idx[base+1] = i1; g_idx[base+2] = i2;
    g_w[base] = r0*inv; g_w[base+1] = r1*inv; g_w[base+2] = r2*inv;
}

__global__ void bnfin_kernel(const float* __restrict__ gamma,
                             const float* __restrict__ beta, int which) {
    int t = threadIdx.x;
    float s = which ? g_s2[t] : g_s1[t];
    float q = which ? g_q2[t] : g_q1[t];
    float mean = s * (1.f / CNT_);
    float var  = q * (1.f / CNT_) - mean * mean;
    float sc = gamma[t] * rsqrtf(var + 1e-5f);
    float bi = beta[t] - mean * sc;
    if (which) { g_scale2[t] = sc; g_bias2[t] = bi; }
    else       { g_scale1[t] = sc; g_bias1[t] = bi; }
}

__global__ void out_kernel(float* __restrict__ out) {
    int i = blockIdx.x * blockDim.x + threadIdx.x;
    int o = (i >> 11) & 255;
    float sc = g_scale2[o], bi = g_bias2[o];
    float4 v = ((float4*)out)[i];
    v.x = fmaxf(fmaf(v.x, sc, bi), 0.f);
    v.y = fmaxf(fmaf(v.y, sc, bi), 0.f);
    v.z = fmaxf(fmaf(v.z, sc, bi), 0.f);
    v.w = fmaxf(fmaf(v.w, sc, bi), 0.f);
    ((float4*)out)[i] = v;
}

// ---------------- GEMM core (fp16 m16n8k16, tile 128o x 128n) ----------------
// 8 warps as (wo 0..3)x(wn 0..1); warp tile 32o x 64n = 2 mtiles x 8 ntiles.
// Double-buffered stage, ONE __syncthreads per chunk.

__device__ __forceinline__ void ldgA(const float* W, int ws, int o0, int c, int tid,
                                     float4* ra) {
    const float* s = W + (size_t)(o0 + (tid & 127)) * ws + c*16 + (tid >> 7) * 8;
    ra[0] = *(const float4*)s; ra[1] = *(const float4*)(s + 4);
}
__device__ __forceinline__ void stsA(unsigned* As, const float4* ra, int tid) {
    unsigned w0[4];
    w0[0] = pack2(ra[0].x, ra[0].y); w0[1] = pack2(ra[0].z, ra[0].w);
    w0[2] = pack2(ra[1].x, ra[1].y); w0[3] = pack2(ra[1].z, ra[1].w);
    *(uint4*)(As + (tid & 127)*APW + (tid >> 7) * 4) = *(uint4*)w0;
}
__device__ __forceinline__ void ldgB(const float* X, int cs, int c, int tid,
                                     float4& r0, float4& r1) {
    int k2 = tid >> 5, ng = (tid & 31) * 4;
    const float* s = X + (size_t)(c*16 + 2*k2) * cs + ng;
    r0 = *(const float4*)s;
    r1 = *(const float4*)(s + cs);
}
__device__ __forceinline__ void stsB(unsigned* Bs, float4 r0, float4 r1, int tid) {
    int k2 = tid >> 5, ng = (tid & 31) * 4;
    unsigned w[4];
    w[0] = pack2(r0.x, r1.x); w[1] = pack2(r0.y, r1.y);
    w[2] = pack2(r0.z, r1.z); w[3] = pack2(r0.w, r1.w);
    *(uint4*)(Bs + k2*BPW + ng) = *(uint4*)w;
}

__device__ __forceinline__ void frag_mma16(const unsigned* As, const unsigned* Bs,
                                           int wo, int wn, int g, int t,
                                           float acc[2][8][4]) {
    unsigned af[2][4], bf[8][2];
    #pragma unroll
    for (int mi = 0; mi < 2; mi++) {
        int row = wo*32 + mi*16 + g;
        af[mi][0] = As[row*APW + t];
        af[mi][1] = As[(row+8)*APW + t];
        af[mi][2] = As[row*APW + t + 4];
        af[mi][3] = As[(row+8)*APW + t + 4];
    }
    #pragma unroll
    for (int ni = 0; ni < 8; ni++) {
        int nb = wn*64 + ni*8 + g;
        bf[ni][0] = Bs[t*BPW + nb];
        bf[ni][1] = Bs[(t+4)*BPW + nb];
    }
    #pragma unroll
    for (int mi = 0; mi < 2; mi++)
        #pragma unroll
        for (int ni = 0; ni < 8; ni++)
            hmma16(acc[mi][ni], af[mi], bf[ni]);
}

__device__ __forceinline__ void mainloop16(float* sm, const float* W, int ws, int o0,
                                           const float* X, int cs,
                                           float acc[2][8][4]) {
    int tid = threadIdx.x, lane = tid & 31, w = tid >> 5;
    int wo = w >> 1, wn = w & 1, g = lane >> 2, t = lane & 3;
    unsigned* s0 = (unsigned*)sm;
    unsigned* s1 = (unsigned*)sm + STG;
    float4 ra[2], rb0, rb1;
    ldgA(W, ws, o0, 0, tid, ra);
    ldgB(X, cs, 0, tid, rb0, rb1);
    stsA(s0, ra, tid);
    stsB(s0 + OFF_BW, rb0, rb1, tid);
    ldgA(W, ws, o0, 1, tid, ra);
    ldgB(X, cs, 1, tid, rb0, rb1);
    __syncthreads();
    for (int c = 0; c < 16; c++) {
        unsigned* cur = (c & 1) ? s1 : s0;
        unsigned* nxt = (c & 1) ? s0 : s1;
        if (c < 15) {                       // stage chunk c+1 into idle buffer
            stsA(nxt, ra, tid);
            stsB(nxt + OFF_BW, rb0, rb1, tid);
        }
        if (c < 14) {                       // prefetch chunk c+2
            ldgA(W, ws, o0, c+2, tid, ra);
            ldgB(X, cs, c+2, tid, rb0, rb1);
        }
        frag_mma16(cur, cur + OFF_BW, wo, wn, g, t, acc);
        __syncthreads();                    // one barrier: sts(c+1) visible + compute(c) done
    }
}

__device__ __forceinline__ void acc_to_ys(float* sm, float acc[2][8][4],
                                          int wo, int wn, int g, int t) {
    #pragma unroll
    for (int mi = 0; mi < 2; mi++)
        #pragma unroll
        for (int ni = 0; ni < 8; ni++) {
            int orow = wo*32 + mi*16 + g;
            int ncol = wn*64 + ni*8 + 2*t;
            sm[ncol*YP + orow]       = acc[mi][ni][0];
            sm[(ncol+1)*YP + orow]   = acc[mi][ni][1];
            sm[ncol*YP + orow+8]     = acc[mi][ni][2];
            sm[(ncol+1)*YP + orow+8] = acc[mi][ni][3];
        }
}

// ---------------- gemmG: G[z][m][o] = W1a @ kf (persistent tiles) ----------------
__global__ __launch_bounds__(256, 2) void gemmG(const float* __restrict__ kf,
                                                const float* __restrict__ W1) {
    extern __shared__ float sm[];
    int tid = threadIdx.x, lane = tid & 31, w = tid >> 5;
    int wo = w >> 1, wn = w & 1, g = lane >> 2, t = lane & 3;
    volatile int* s_tile = (volatile int*)(sm + OFF_T);
    for (;;) {
        if (tid == 0) *s_tile = atomicAdd(&g_tk[0], 1);
        __syncthreads();
        int tile = *s_tile;
        if (tile >= NT_G) break;
        int z = tile >> 3, o0 = ((tile >> 2) & 1) * 128, m0 = (tile & 3) * 128;
        int b = z >> 2, r = z & 3;
        float acc[2][8][4] = {};
        const float* X = kf + (size_t)b * (C_*NR_*M_) + (size_t)r * M_ + m0;
        mainloop16(sm, W1, 512, o0, X, NR_*M_, acc);
        acc_to_ys(sm, acc, wo, wn, g, t);
        __syncthreads();
        float* Gz = g_G + ((size_t)z * M_ + m0) * C_ + o0;
        for (int it = 0; it < 16; it++) {
            int m = it*8 + w;
            #pragma unroll
            for (int j = 0; j < 4; j++) {
                int o = lane + 32*j;
                Gz[(size_t)m * C_ + o] = sm[m*YP + o];
            }
        }
        __syncthreads();
    }
}

// ---------------- gemmY1: y1 = W1b@uf + gather(G); BN1 stats ----------------
__global__ __launch_bounds__(256, 2) void gemmY1(const float* __restrict__ uf,
                                                 const float* __restrict__ W1) {
    extern __shared__ float sm[];
    int tid = threadIdx.x, lane = tid & 31, w = tid >> 5;
    int wo = w >> 1, wn = w & 1, g = lane >> 2, t = lane & 3;
    volatile int* s_tile = (volatile int*)(sm + OFF_T);
    for (;;) {
        if (tid == 0) *s_tile = atomicAdd(&g_tk[1], 1);
        __syncthreads();
        int tile = *s_tile;
        if (tile >= NT_Y) break;
        int z = tile >> 5, o0 = ((tile >> 4) & 1) * 128, n0 = (tile & 15) * 128;
        int b = z >> 2, r = z & 3;
        float acc[2][8][4] = {};
        const float* X = uf + (size_t)b * (C_*NR_*N_) + (size_t)r * N_ + n0;
        mainloop16(sm, W1 + 256, 512, o0, X, NR_*N_, acc);
        acc_to_ys(sm, acc, wo, wn, g, t);
        // load interp data + zero local stats
        for (int l = tid; l < 384; l += 256) {
            sm[OFF_W + l]         = g_w  [(b * N_ + n0) * 3 + l];
            ((int*)sm)[OFF_I + l] = g_idx[(b * N_ + n0) * 3 + l];
        }
        if (tid < 128) { sm[OFF_S + tid] = 0.f; sm[OFF_Q + tid] = 0.f; }
        __syncthreads();
        // gather + BN1 stats (warp-per-n, lane-per-o)
        const float* Gz = g_G + (size_t)z * M_ * C_ + o0;
        float s4[4] = {}, q4[4] = {};
        for (int it = 0; it < 16; it++) {
            int n = it*8 + w;
            float w0 = sm[OFF_W + n*3], w1 = sm[OFF_W + n*3+1], w2 = sm[OFF_W + n*3+2];
            const float* G0 = Gz + (size_t)((int*)sm)[OFF_I + n*3]     * C_;
            const float* G1 = Gz + (size_t)((int*)sm)[OFF_I + n*3 + 1] * C_;
            const float* G2 = Gz + (size_t)((int*)sm)[OFF_I + n*3 + 2] * C_;
            #pragma unroll
            for (int j = 0; j < 4; j++) {
                int o = lane + 32*j;
                float v = sm[n*YP + o] + w0*G0[o] + w1*G1[o] + w2*G2[o];
                sm[n*YP + o] = v;
                s4[j] += v; q4[j] += v*v;
            }
        }
        #pragma unroll
        for (int j = 0; j < 4; j++) {
            atomicAdd(&sm[OFF_S + lane + 32*j], s4[j]);
            atomicAdd(&sm[OFF_Q + lane + 32*j], q4[j]);
        }
        __syncthreads();
        if (tid < 128) {
            atomicAdd(&g_s1[o0 + tid], sm[OFF_S + tid]);
            atomicAdd(&g_q1[o0 + tid], sm[OFF_Q + tid]);
        }
        float* y1z = g_y1 + (size_t)z * C_ * N_ + (size_t)o0 * N_ + n0;
        for (int it = 0; it < 16; it++) {
            int o = it*8 + w;
            #pragma unroll
            for (int j = 0; j < 4; j++) {
                int n = lane + 32*j;
                y1z[(size_t)o * N_ + n] = sm[n*YP + o];
            }
        }
        __syncthreads();
    }
}

// ---------------- gemmZ: out = W2 @ relu(bn1(y1)); BN2 stats ----------------
__global__ __launch_bounds__(256, 2) void gemmZ(const float* __restrict__ W2,
                                                float* __restrict__ out) {
    extern __shared__ float sm[];
    int tid = threadIdx.x, lane = tid & 31, w = tid >> 5;
    int wo = w >> 1, wn = w & 1, g = lane >> 2, t = lane & 3;
    int k2 = tid >> 5;
    unsigned* s0 = (unsigned*)sm;
    unsigned* s1 = (unsigned*)sm + STG;
    volatile int* s_tile = (volatile int*)(sm + OFF_T);
    for (;;) {
        if (tid == 0) *s_tile = atomicAdd(&g_tk[2], 1);
        __syncthreads();
        int tile = *s_tile;
        if (tile >= NT_Y) break;
        int z = tile >> 5, o0 = ((tile >> 4) & 1) * 128, n0 = (tile & 15) * 128;
        int b = z >> 2, r = z & 3;
        float acc[2][8][4] = {};
        const float* y1z = g_y1 + (size_t)z * C_ * N_ + n0;
        float4 ra[2], rb0, rb1;

        // prologue: stage chunk 0, prefetch chunk 1
        ldgA(W2, 256, o0, 0, tid, ra);
        ldgB(y1z, N_, 0, tid, rb0, rb1);
        {
            float sc0 = g_scale1[2*k2],     bi0 = g_bias1[2*k2];
            float sc1 = g_scale1[2*k2 + 1], bi1 = g_bias1[2*k2 + 1];
            float4 v0 = rb0, v1 = rb1;
            v0.x = fmaxf(fmaf(v0.x, sc0, bi0), 0.f); v0.y = fmaxf(fmaf(v0.y, sc0, bi0), 0.f);
            v0.z = fmaxf(fmaf(v0.z, sc0, bi0), 0.f); v0.w = fmaxf(fmaf(v0.w, sc0, bi0), 0.f);
            v1.x = fmaxf(fmaf(v1.x, sc1, bi1), 0.f); v1.y = fmaxf(fmaf(v1.y, sc1, bi1), 0.f);
            v1.z = fmaxf(fmaf(v1.z, sc1, bi1), 0.f); v1.w = fmaxf(fmaf(v1.w, sc1, bi1), 0.f);
            stsB(s0 + OFF_BW, v0, v1, tid);
        }
        stsA(s0, ra, tid);
        ldgA(W2, 256, o0, 1, tid, ra);
        ldgB(y1z, N_, 1, tid, rb0, rb1);
        __syncthreads();
        for (int c = 0; c < 16; c++) {
            unsigned* cur = (c & 1) ? s1 : s0;
            unsigned* nxt = (c & 1) ? s0 : s1;
            if (c < 15) {                   // stage chunk c+1 with BN1+ReLU fused
                float sc0 = g_scale1[(c+1)*16 + 2*k2],     bi0 = g_bias1[(c+1)*16 + 2*k2];
                float sc1 = g_scale1[(c+1)*16 + 2*k2 + 1], bi1 = g_bias1[(c+1)*16 + 2*k2 + 1];
                float4 v0 = rb0, v1 = rb1;
                v0.x = fmaxf(fmaf(v0.x, sc0, bi0), 0.f); v0.y = fmaxf(fmaf(v0.y, sc0, bi0), 0.f);
                v0.z = fmaxf(fmaf(v0.z, sc0, bi0), 0.f); v0.w = fmaxf(fmaf(v0.w, sc0, bi0), 0.f);
                v1.x = fmaxf(fmaf(v1.x, sc1, bi1), 0.f); v1.y = fmaxf(fmaf(v1.y, sc1, bi1), 0.f);
                v1.z = fmaxf(fmaf(v1.z, sc1, bi1), 0.f); v1.w = fmaxf(fmaf(v1.w, sc1, bi1), 0.f);
                stsB(nxt + OFF_BW, v0, v1, tid);
                stsA(nxt, ra, tid);
            }
            if (c < 14) {
                ldgA(W2, 256, o0, c+2, tid, ra);
                ldgB(y1z, N_, c+2, tid, rb0, rb1);
            }
            frag_mma16(cur, cur + OFF_BW, wo, wn, g, t, acc);
            __syncthreads();
        }
        // BN2 stats from pre-BN accumulators
        if (tid < 128) { sm[OFF_S + tid] = 0.f; sm[OFF_Q + tid] = 0.f; }
        __syncthreads();
        #pragma unroll
        for (int mi = 0; mi < 2; mi++) {
            float sa = 0.f, qa = 0.f, sb = 0.f, qb = 0.f;
            #pragma unroll
            for (int ni = 0; ni < 8; ni++) {
                float a0 = acc[mi][ni][0], a1 = acc[mi][ni][1];
                float a2 = acc[mi][ni][2], a3 = acc[mi][ni][3];
                sa += a0 + a1;  qa += a0*a0 + a1*a1;
                sb += a2 + a3;  qb += a2*a2 + a3*a3;
            }
            int orow = wo*32 + mi*16 + g;
            atomicAdd(&sm[OFF_S + orow],     sa);
            atomicAdd(&sm[OFF_Q + orow],     qa);
            atomicAdd(&sm[OFF_S + orow + 8], sb);
            atomicAdd(&sm[OFF_Q + orow + 8], qb);
        }
        __syncthreads();
        if (tid < 128) {
            atomicAdd(&g_s2[o0 + tid], sm[OFF_S + tid]);
            atomicAdd(&g_q2[o0 + tid], sm[OFF_Q + tid]);
        }
        __syncthreads();
        acc_to_ys(sm, acc, wo, wn, g, t);
        __syncthreads();
        float* ob = out + ((size_t)(b*256 + o0) * 4 + r) * 2048 + n0;
        for (int it = 0; it < 16; it++) {
            int o = it*8 + w;
            #pragma unroll
            for (int j = 0; j < 4; j++) {
                int n = lane + 32*j;
                ob[(size_t)o * (4*2048) + n] = sm[n*YP + o];
            }
        }
        __syncthreads();
    }
}

// ---------------- launch ----------------
extern "C" void kernel_launch(void* const* d_in, const int* in_sizes, int n_in,
                              void* d_out, int out_size) {
    const float* unknown = (const float*)d_in[0];
    const float* known   = (const float*)d_in[1];
    const float* uf      = (const float*)d_in[2];
    const float* kf      = (const float*)d_in[3];
    const float* W1      = (const float*)d_in[4];
    const float* g1      = (const float*)d_in[5];
    const float* b1      = (const float*)d_in[6];
    const float* W2      = (const float*)d_in[7];
    const float* g2      = (const float*)d_in[8];
    const float* b2      = (const float*)d_in[9];
    float* out = (float*)d_out;

    static int inited = 0;
    if (!inited) {
        cudaFuncSetAttribute(gemmG,  cudaFuncAttributeMaxDynamicSharedMemorySize, SMEM_BYTES);
        cudaFuncSetAttribute(gemmY1, cudaFuncAttributeMaxDynamicSharedMemorySize, SMEM_BYTES);
        cudaFuncSetAttribute(gemmZ,  cudaFuncAttributeMaxDynamicSharedMemorySize, SMEM_BYTES);
        inited = 1;
    }

    zero_stats_kernel<<<1, 256>>>();
    knn_kernel<<<dim3(N_/256, B_), 256>>>(unknown, known);
    gemmG<<<GRID_P, 256, SMEM_BYTES>>>(kf, W1);
    gemmY1<<<GRID_P, 256, SMEM_BYTES>>>(uf, W1);
    bnfin_kernel<<<1, 256>>>(g1, b1, 0);
    gemmZ<<<GRID_P, 256, SMEM_BYTES>>>(W2, out);
    bnfin_kernel<<<1, 256>>>(g2, b2, 1);
    out_kernel<<<(B_*256*NR_*N_/4) / 256, 256>>>(out);
}